// round 5
// baseline (speedup 1.0000x reference)
#include <cuda_runtime.h>

#define N_NODES 50000
#define N_EDGES 1600000
#define R_REL 7
#define DIM 128
#define G_GRAPHS 64
#define N_LAYERS 3
#define Y_ELEMS ((long)N_NODES * R_REL * DIM)   // 44.8M floats

// Scratch (no cudaMalloc allowed): device globals.
__device__ float g_x[N_NODES * DIM];
__device__ float g_x2[N_NODES * DIM];
__device__ float g_y[N_NODES * R_REL * DIM];    // y[r][n][d]

// ---------------------------------------------------------------------------
// x = emb[unit_type]
// ---------------------------------------------------------------------------
__global__ void gather_emb_kernel(const int* __restrict__ ut,
                                  const float* __restrict__ emb,
                                  float* __restrict__ x) {
    int t = blockIdx.x * blockDim.x + threadIdx.x;
    if (t >= N_NODES * (DIM / 4)) return;
    int n = t >> 5;          // 32 float4 per row
    int c = t & 31;
    float4 v = ((const float4*)(emb + (long)ut[n] * DIM))[c];
    ((float4*)(x + (long)n * DIM))[c] = v;
}

__global__ void zero_gf_kernel(float* __restrict__ out) {
    int t = blockIdx.x * blockDim.x + threadIdx.x;
    if (t < G_GRAPHS * DIM) out[t] = 0.f;
}

// ---------------------------------------------------------------------------
// 8-way GEMM, K=128 fixed:
//   blockIdx.y = r in [0,7):  y[r] = x @ W_rel_block[r]          (no bias)
//   blockIdx.y = 7:           h    = x @ W_loop + (br + bl)      (init of h)
// BM=128, BN=128, BK=8, 256 threads, 8x8 accumulators per thread.
// ---------------------------------------------------------------------------
#define BM 128
#define BN 128
#define BK 8

__global__ __launch_bounds__(256) void gemm8_kernel(
    const float* __restrict__ x,
    const float* __restrict__ Wrel,   // (R*D, D) for this layer
    const float* __restrict__ Wloop,  // (D, D)   for this layer
    const float* __restrict__ br, const float* __restrict__ bl,
    float* __restrict__ y, float* __restrict__ h) {
    __shared__ float As[BK][BM];
    __shared__ float Bs[BK][BN];

    int tid = threadIdx.x;
    int r   = blockIdx.y;                 // 0..7
    int m0  = blockIdx.x * BM;
    const float* B = (r < R_REL) ? (Wrel + (long)r * DIM * DIM) : Wloop;
    float* out     = (r < R_REL) ? (y + (long)r * N_NODES * DIM) : h;

    int trow = (tid >> 4) * 8;            // 0..120
    int tcol = (tid & 15) * 8;            // 0..120

    float acc[8][8];
#pragma unroll
    for (int i = 0; i < 8; i++)
#pragma unroll
        for (int j = 0; j < 8; j++) acc[i][j] = 0.f;

    for (int k0 = 0; k0 < DIM; k0 += BK) {
        // A tile (128 rows x 8 k), stored transposed As[k][m]
        {
            int ar = tid >> 1, ac = (tid & 1) * 4;
            int row = m0 + ar;
            float4 a = make_float4(0.f, 0.f, 0.f, 0.f);
            if (row < N_NODES)
                a = *(const float4*)(x + (long)row * DIM + k0 + ac);
            As[ac + 0][ar] = a.x; As[ac + 1][ar] = a.y;
            As[ac + 2][ar] = a.z; As[ac + 3][ar] = a.w;
        }
        // B tile (8 k x 128 cols)
        {
            int brr = tid >> 5, bc = (tid & 31) * 4;
            *(float4*)&Bs[brr][bc] = *(const float4*)(B + (long)(k0 + brr) * DIM + bc);
        }
        __syncthreads();
#pragma unroll
        for (int kk = 0; kk < BK; kk++) {
            float a[8], b[8];
            *(float4*)a       = *(float4*)&As[kk][trow];
            *(float4*)(a + 4) = *(float4*)&As[kk][trow + 4];
            *(float4*)b       = *(float4*)&Bs[kk][tcol];
            *(float4*)(b + 4) = *(float4*)&Bs[kk][tcol + 4];
#pragma unroll
            for (int i = 0; i < 8; i++)
#pragma unroll
                for (int j = 0; j < 8; j++)
                    acc[i][j] = fmaf(a[i], b[j], acc[i][j]);
        }
        __syncthreads();
    }

    float bb[8];
    if (r == R_REL) {
#pragma unroll
        for (int j = 0; j < 8; j++) bb[j] = br[tcol + j] + bl[tcol + j];
    } else {
#pragma unroll
        for (int j = 0; j < 8; j++) bb[j] = 0.f;
    }

#pragma unroll
    for (int i = 0; i < 8; i++) {
        int row = m0 + trow + i;
        if (row < N_NODES) {
            float4 v0, v1;
            v0.x = acc[i][0] + bb[0]; v0.y = acc[i][1] + bb[1];
            v0.z = acc[i][2] + bb[2]; v0.w = acc[i][3] + bb[3];
            v1.x = acc[i][4] + bb[4]; v1.y = acc[i][5] + bb[5];
            v1.z = acc[i][6] + bb[6]; v1.w = acc[i][7] + bb[7];
            *(float4*)(out + (long)row * DIM + tcol)     = v0;
            *(float4*)(out + (long)row * DIM + tcol + 4) = v1;
        }
    }
}

// ---------------------------------------------------------------------------
// Scatter: h[node_out, :] += ew * y[rel][node_in, :]
// One warp per edge, 32 lanes x float4. Destination h is 25.6 MB (L2-resident).
// ---------------------------------------------------------------------------
__global__ void scatter_kernel(const int* __restrict__ node_in,
                               const int* __restrict__ node_out,
                               const int* __restrict__ rel,
                               const float* __restrict__ ew,
                               const float* __restrict__ y,
                               float* __restrict__ h) {
    int w = (blockIdx.x * blockDim.x + threadIdx.x) >> 5;
    if (w >= N_EDGES) return;
    int lane = threadIdx.x & 31;
    int nin  = node_in[w];
    int nout = node_out[w];
    int r    = rel[w];
    float wt = ew[w];
    float4 v = ((const float4*)(y + ((long)r * N_NODES + nin) * DIM))[lane];
    v.x *= wt; v.y *= wt; v.z *= wt; v.w *= wt;
    float* dst = h + (long)nout * DIM + lane * 4;
    asm volatile("red.global.add.v4.f32 [%0], {%1,%2,%3,%4};"
                 :: "l"(dst), "f"(v.x), "f"(v.y), "f"(v.z), "f"(v.w)
                 : "memory");
}

// ---------------------------------------------------------------------------
// In-place ReLU on h (after all atomics drained).
// ---------------------------------------------------------------------------
__global__ void relu_kernel(float* __restrict__ h) {
    int t = blockIdx.x * blockDim.x + threadIdx.x;
    if (t >= N_NODES * (DIM / 4)) return;
    float4 v = ((float4*)h)[t];
    v.x = fmaxf(v.x, 0.f); v.y = fmaxf(v.y, 0.f);
    v.z = fmaxf(v.z, 0.f); v.w = fmaxf(v.w, 0.f);
    ((float4*)h)[t] = v;
}

// ---------------------------------------------------------------------------
// Graph feature: segment-sum of final x by (sorted) node2graph.
// ---------------------------------------------------------------------------
#define NODES_PER_BLOCK 128
__global__ void graph_sum_kernel(const float* __restrict__ x,
                                 const int* __restrict__ n2g,
                                 float* __restrict__ gf) {
    int d = threadIdx.x;  // 0..127
    int start = blockIdx.x * NODES_PER_BLOCK;
    if (start >= N_NODES) return;
    int end = min(start + NODES_PER_BLOCK, N_NODES);
    float acc = 0.f;
    int cur = n2g[start];
    for (int nd = start; nd < end; nd++) {
        int g = n2g[nd];                       // broadcast load
        float v = x[(long)nd * DIM + d];
        if (g != cur) {
            atomicAdd(&gf[cur * DIM + d], acc);
            acc = 0.f;
            cur = g;
        }
        acc += v;
    }
    atomicAdd(&gf[cur * DIM + d], acc);
}

// ---------------------------------------------------------------------------
extern "C" void kernel_launch(void* const* d_in, const int* in_sizes, int n_in,
                              void* d_out, int out_size) {
    const int*   unit_type   = (const int*)d_in[0];
    const int*   node_in     = (const int*)d_in[1];
    const int*   node_out    = (const int*)d_in[2];
    const int*   relation    = (const int*)d_in[3];
    const float* edge_weight = (const float*)d_in[4];
    const int*   node2graph  = (const int*)d_in[5];
    const float* emb         = (const float*)d_in[6];
    const float* W_rel       = (const float*)d_in[7];
    const float* b_rel       = (const float*)d_in[8];
    const float* W_loop      = (const float*)d_in[9];
    const float* b_loop      = (const float*)d_in[10];

    float* out = (float*)d_out;
    float* gf         = out;                     // [G, D]
    float* xout_final = out + G_GRAPHS * DIM;    // [N, D]

    float *xA, *xB, *y;
    cudaGetSymbolAddress((void**)&xA, g_x);
    cudaGetSymbolAddress((void**)&xB, g_x2);
    cudaGetSymbolAddress((void**)&y,  g_y);

    gather_emb_kernel<<<(N_NODES * (DIM / 4) + 255) / 256, 256>>>(unit_type, emb, xA);
    zero_gf_kernel<<<(G_GRAPHS * DIM + 255) / 256, 256>>>(gf);

    const int gemm_gx = (N_NODES + BM - 1) / BM;          // 391
    const int relu_grid = (N_NODES * (DIM / 4) + 255) / 256;

    const float* xin = xA;
    for (int l = 0; l < N_LAYERS; l++) {
        float* h = (l == N_LAYERS - 1) ? xout_final
                                       : ((xin == xA) ? xB : xA);
        gemm8_kernel<<<dim3(gemm_gx, R_REL + 1), 256>>>(
            xin,
            W_rel  + (long)l * (R_REL * DIM) * DIM,
            W_loop + (long)l * DIM * DIM,
            b_rel  + (long)l * DIM,
            b_loop + (long)l * DIM,
            y, h);
        scatter_kernel<<<(N_EDGES * 32 + 255) / 256, 256>>>(
            node_in, node_out, relation, edge_weight, y, h);
        relu_kernel<<<relu_grid, 256>>>(h);
        xin = h;
    }

    graph_sum_kernel<<<(N_NODES + NODES_PER_BLOCK - 1) / NODES_PER_BLOCK,
                       NODES_PER_BLOCK>>>(xout_final, node2graph, gf);
}

// round 8
// speedup vs baseline: 1.0722x; 1.0722x over previous
#include <cuda_runtime.h>

#define N_NODES 50000
#define N_EDGES 1600000
#define R_REL 7
#define DIM 128
#define G_GRAPHS 64
#define N_LAYERS 3

// Scratch (no cudaMalloc allowed): device globals.
__device__ float g_x[N_NODES * DIM];
__device__ float g_x2[N_NODES * DIM];
__device__ float g_y[N_NODES * R_REL * DIM];    // y[r][n][d], 179 MB
__device__ int   g_cnt[N_NODES];                // in-degree / fill cursor
__device__ int   g_ptr[N_NODES + 1];            // CSR row pointers
__device__ int2  g_epack[N_EDGES];              // {r*N+nin, ew bits} in CSR order

// ---------------------------------------------------------------------------
// x = emb[unit_type]
// ---------------------------------------------------------------------------
__global__ void gather_emb_kernel(const int* __restrict__ ut,
                                  const float* __restrict__ emb,
                                  float* __restrict__ x) {
    int t = blockIdx.x * blockDim.x + threadIdx.x;
    if (t >= N_NODES * (DIM / 4)) return;
    int n = t >> 5;
    int c = t & 31;
    float4 v = ((const float4*)(emb + (long)ut[n] * DIM))[c];
    ((float4*)(x + (long)n * DIM))[c] = v;
}

__global__ void zero_gf_kernel(float* __restrict__ out) {
    int t = blockIdx.x * blockDim.x + threadIdx.x;
    if (t < G_GRAPHS * DIM) out[t] = 0.f;
}

// ---------------------------------------------------------------------------
// CSR build: histogram -> scan -> fill (runs once per launch)
// ---------------------------------------------------------------------------
__global__ void zero_cnt_kernel(int* __restrict__ cnt) {
    int t = blockIdx.x * blockDim.x + threadIdx.x;
    if (t < N_NODES) cnt[t] = 0;
}

__global__ void count_kernel(const int* __restrict__ node_out,
                             int* __restrict__ cnt) {
    int e = blockIdx.x * blockDim.x + threadIdx.x;
    if (e < N_EDGES) atomicAdd(&cnt[node_out[e]], 1);
}

// Single-block Hillis-Steele chunked scan. Writes ptr[] (exclusive, N+1) and
// resets cnt[] to the exclusive prefix to serve as the fill cursor.
__global__ void scan_kernel(int* __restrict__ cnt, int* __restrict__ ptr) {
    __shared__ int s[1024];
    __shared__ int carry;
    if (threadIdx.x == 0) { carry = 0; ptr[0] = 0; }
    __syncthreads();
    for (int base = 0; base < N_NODES; base += 1024) {
        int i = base + threadIdx.x;
        int v = (i < N_NODES) ? cnt[i] : 0;
        s[threadIdx.x] = v;
        __syncthreads();
#pragma unroll
        for (int off = 1; off < 1024; off <<= 1) {
            int t = (threadIdx.x >= off) ? s[threadIdx.x - off] : 0;
            __syncthreads();
            s[threadIdx.x] += t;
            __syncthreads();
        }
        if (i < N_NODES) {
            int inc = carry + s[threadIdx.x];
            ptr[i + 1] = inc;       // exclusive ptr
            cnt[i] = inc - v;       // fill cursor starts at ptr[i]
        }
        __syncthreads();
        if (threadIdx.x == 1023) carry += s[1023];
        __syncthreads();
    }
}

__global__ void fill_kernel(const int* __restrict__ node_in,
                            const int* __restrict__ node_out,
                            const int* __restrict__ rel,
                            const float* __restrict__ ew,
                            int* __restrict__ cursor,
                            int2* __restrict__ epack) {
    int e = blockIdx.x * blockDim.x + threadIdx.x;
    if (e >= N_EDGES) return;
    int nout = node_out[e];
    int pos = atomicAdd(&cursor[nout], 1);
    epack[pos] = make_int2(rel[e] * N_NODES + node_in[e],
                           __float_as_int(ew[e]));
}

// ---------------------------------------------------------------------------
// 8-way GEMM with packed fp32x2 FMA, K=128 fixed:
//   blockIdx.y = r in [0,7):  y[r] = x @ W_rel_block[r]
//   blockIdx.y = 7:           h    = x @ W_loop + (br + bl)
// BM=128, BN=128, BK=8, 256 threads, 8x8 per thread via 32 fma.rn.f32x2.
// A stored duplicated in shared (float2{a,a}) so FFMA2 needs no packing movs.
// ---------------------------------------------------------------------------
#define BM 128
#define BN 128
#define BK 8

__global__ __launch_bounds__(256) void gemm8_kernel(
    const float* __restrict__ x,
    const float* __restrict__ Wrel,   // (R*D, D)
    const float* __restrict__ Wloop,  // (D, D)
    const float* __restrict__ br, const float* __restrict__ bl,
    float* __restrict__ y, float* __restrict__ h) {
    __shared__ float2 As2[BK][BM];    // duplicated a-values, 8 KB
    __shared__ float  Bs[BK][BN];     // 4 KB

    int tid = threadIdx.x;
    int r   = blockIdx.y;
    int m0  = blockIdx.x * BM;
    const float* B = (r < R_REL) ? (Wrel + (long)r * DIM * DIM) : Wloop;
    float* out     = (r < R_REL) ? (y + (long)r * N_NODES * DIM) : h;

    int trow = (tid >> 4) * 8;        // 0..120
    int tcol = (tid & 15) * 8;        // 0..120

    unsigned long long acc2[8][4];    // [i][j-pair], each = packed float2
#pragma unroll
    for (int i = 0; i < 8; i++)
#pragma unroll
        for (int j = 0; j < 4; j++) acc2[i][j] = 0ull;

    for (int k0 = 0; k0 < DIM; k0 += BK) {
        // A tile: 128 rows x 8 k, duplicated, transposed As2[k][m] = {a,a}
        {
            int ar = tid >> 1, ac = (tid & 1) * 4;
            int row = m0 + ar;
            float4 a = make_float4(0.f, 0.f, 0.f, 0.f);
            if (row < N_NODES)
                a = *(const float4*)(x + (long)row * DIM + k0 + ac);
            As2[ac + 0][ar] = make_float2(a.x, a.x);
            As2[ac + 1][ar] = make_float2(a.y, a.y);
            As2[ac + 2][ar] = make_float2(a.z, a.z);
            As2[ac + 3][ar] = make_float2(a.w, a.w);
        }
        // B tile: 8 k x 128 cols
        {
            int brr = tid >> 5, bc = (tid & 31) * 4;
            *(float4*)&Bs[brr][bc] = *(const float4*)(B + (long)(k0 + brr) * DIM + bc);
        }
        __syncthreads();
#pragma unroll
        for (int kk = 0; kk < BK; kk++) {
            unsigned long long a2[8], b2[4];
            // 8 duplicated a values = 64B contiguous -> 4 LDS.128
            const ulonglong2* ap = (const ulonglong2*)&As2[kk][trow];
            ulonglong2 A01 = ap[0], A23 = ap[1], A45 = ap[2], A67 = ap[3];
            a2[0] = A01.x; a2[1] = A01.y; a2[2] = A23.x; a2[3] = A23.y;
            a2[4] = A45.x; a2[5] = A45.y; a2[6] = A67.x; a2[7] = A67.y;
            // 8 b values = 4 pairs = 32B contiguous -> 2 LDS.128
            const ulonglong2* bp = (const ulonglong2*)&Bs[kk][tcol];
            ulonglong2 B01 = bp[0], B23 = bp[1];
            b2[0] = B01.x; b2[1] = B01.y; b2[2] = B23.x; b2[3] = B23.y;
#pragma unroll
            for (int i = 0; i < 8; i++)
#pragma unroll
                for (int j = 0; j < 4; j++)
                    asm("fma.rn.f32x2 %0, %1, %2, %0;"
                        : "+l"(acc2[i][j]) : "l"(a2[i]), "l"(b2[j]));
        }
        __syncthreads();
    }

    float bb[8];
    if (r == R_REL) {
#pragma unroll
        for (int j = 0; j < 8; j++) bb[j] = br[tcol + j] + bl[tcol + j];
    } else {
#pragma unroll
        for (int j = 0; j < 8; j++) bb[j] = 0.f;
    }

#pragma unroll
    for (int i = 0; i < 8; i++) {
        int row = m0 + trow + i;
        if (row < N_NODES) {
            float o[8];
#pragma unroll
            for (int j = 0; j < 4; j++) {
                float2 p = *(float2*)&acc2[i][j];
                o[2 * j]     = p.x + bb[2 * j];
                o[2 * j + 1] = p.y + bb[2 * j + 1];
            }
            *(float4*)(out + (long)row * DIM + tcol)     = *(float4*)&o[0];
            *(float4*)(out + (long)row * DIM + tcol + 4) = *(float4*)&o[4];
        }
    }
}

// ---------------------------------------------------------------------------
// Atomic-free message gather: one warp per destination node.
//   h[n] = relu( h[n] + sum_{e in CSR[n]} ew_e * y[seg_e] )
// ---------------------------------------------------------------------------
__global__ void gather_msg_kernel(const int* __restrict__ ptr,
                                  const int2* __restrict__ epack,
                                  const float* __restrict__ y,
                                  float* __restrict__ h) {
    int node = (blockIdx.x * blockDim.x + threadIdx.x) >> 5;
    if (node >= N_NODES) return;
    int lane = threadIdx.x & 31;
    int beg = ptr[node], end = ptr[node + 1];

    float4 acc = ((float4*)(h + (long)node * DIM))[lane];

    int i = beg;
    for (; i + 1 < end; i += 2) {
        int2 m0 = epack[i];
        int2 m1 = epack[i + 1];
        float4 v0 = ((const float4*)(y + (long)m0.x * DIM))[lane];
        float4 v1 = ((const float4*)(y + (long)m1.x * DIM))[lane];
        float w0 = __int_as_float(m0.y);
        float w1 = __int_as_float(m1.y);
        acc.x = fmaf(w0, v0.x, acc.x); acc.y = fmaf(w0, v0.y, acc.y);
        acc.z = fmaf(w0, v0.z, acc.z); acc.w = fmaf(w0, v0.w, acc.w);
        acc.x = fmaf(w1, v1.x, acc.x); acc.y = fmaf(w1, v1.y, acc.y);
        acc.z = fmaf(w1, v1.z, acc.z); acc.w = fmaf(w1, v1.w, acc.w);
    }
    if (i < end) {
        int2 m0 = epack[i];
        float4 v0 = ((const float4*)(y + (long)m0.x * DIM))[lane];
        float w0 = __int_as_float(m0.y);
        acc.x = fmaf(w0, v0.x, acc.x); acc.y = fmaf(w0, v0.y, acc.y);
        acc.z = fmaf(w0, v0.z, acc.z); acc.w = fmaf(w0, v0.w, acc.w);
    }
    acc.x = fmaxf(acc.x, 0.f); acc.y = fmaxf(acc.y, 0.f);
    acc.z = fmaxf(acc.z, 0.f); acc.w = fmaxf(acc.w, 0.f);
    ((float4*)(h + (long)node * DIM))[lane] = acc;
}

// ---------------------------------------------------------------------------
// Graph feature: segment-sum of final x by (sorted) node2graph.
// ---------------------------------------------------------------------------
#define NODES_PER_BLOCK 128
__global__ void graph_sum_kernel(const float* __restrict__ x,
                                 const int* __restrict__ n2g,
                                 float* __restrict__ gf) {
    int d = threadIdx.x;
    int start = blockIdx.x * NODES_PER_BLOCK;
    if (start >= N_NODES) return;
    int end = min(start + NODES_PER_BLOCK, N_NODES);
    float acc = 0.f;
    int cur = n2g[start];
    for (int nd = start; nd < end; nd++) {
        int g = n2g[nd];
        float v = x[(long)nd * DIM + d];
        if (g != cur) {
            atomicAdd(&gf[cur * DIM + d], acc);
            acc = 0.f;
            cur = g;
        }
        acc += v;
    }
    atomicAdd(&gf[cur * DIM + d], acc);
}

// ---------------------------------------------------------------------------
extern "C" void kernel_launch(void* const* d_in, const int* in_sizes, int n_in,
                              void* d_out, int out_size) {
    const int*   unit_type   = (const int*)d_in[0];
    const int*   node_in     = (const int*)d_in[1];
    const int*   node_out    = (const int*)d_in[2];
    const int*   relation    = (const int*)d_in[3];
    const float* edge_weight = (const float*)d_in[4];
    const int*   node2graph  = (const int*)d_in[5];
    const float* emb         = (const float*)d_in[6];
    const float* W_rel       = (const float*)d_in[7];
    const float* b_rel       = (const float*)d_in[8];
    const float* W_loop      = (const float*)d_in[9];
    const float* b_loop      = (const float*)d_in[10];

    float* out = (float*)d_out;
    float* gf         = out;                     // [G, D]
    float* xout_final = out + G_GRAPHS * DIM;    // [N, D]

    float *xA, *xB, *y;
    int *cnt, *ptr;
    int2 *epack;
    cudaGetSymbolAddress((void**)&xA,    g_x);
    cudaGetSymbolAddress((void**)&xB,    g_x2);
    cudaGetSymbolAddress((void**)&y,     g_y);
    cudaGetSymbolAddress((void**)&cnt,   g_cnt);
    cudaGetSymbolAddress((void**)&ptr,   g_ptr);
    cudaGetSymbolAddress((void**)&epack, g_epack);

    // CSR build (once per launch)
    zero_cnt_kernel<<<(N_NODES + 255) / 256, 256>>>(cnt);
    count_kernel<<<(N_EDGES + 255) / 256, 256>>>(node_out, cnt);
    scan_kernel<<<1, 1024>>>(cnt, ptr);
    fill_kernel<<<(N_EDGES + 255) / 256, 256>>>(node_in, node_out, relation,
                                                edge_weight, cnt, epack);

    gather_emb_kernel<<<(N_NODES * (DIM / 4) + 255) / 256, 256>>>(unit_type, emb, xA);
    zero_gf_kernel<<<(G_GRAPHS * DIM + 255) / 256, 256>>>(gf);

    const int gemm_gx = (N_NODES + BM - 1) / BM;          // 391
    const int gmsg_grid = (N_NODES * 32 + 255) / 256;

    const float* xin = xA;
    for (int l = 0; l < N_LAYERS; l++) {
        float* h = (l == N_LAYERS - 1) ? xout_final
                                       : ((xin == xA) ? xB : xA);
        gemm8_kernel<<<dim3(gemm_gx, R_REL + 1), 256>>>(
            xin,
            W_rel  + (long)l * (R_REL * DIM) * DIM,
            W_loop + (long)l * DIM * DIM,
            b_rel  + (long)l * DIM,
            b_loop + (long)l * DIM,
            y, h);
        gather_msg_kernel<<<gmsg_grid, 256>>>(ptr, epack, y, h);
        xin = h;
    }

    graph_sum_kernel<<<(N_NODES + NODES_PER_BLOCK - 1) / NODES_PER_BLOCK,
                       NODES_PER_BLOCK>>>(xout_final, node2graph, gf);
}